// round 1
// baseline (speedup 1.0000x reference)
#include <cuda_runtime.h>

#define NN 50000
#define EE 850000
#define HDIM 128

// ---------------- scratch (device globals; no allocation allowed) ----------
__device__ float g_h0[NN * HDIM];
__device__ float g_h1[NN * HDIM];
__device__ float g_feat[NN * HDIM];
__device__ float g_el[NN * 4];
__device__ float g_er[NN * 4];
__device__ int   g_deg[NN];
__device__ int   g_rowptr[NN + 1];
__device__ int   g_cursor[NN];
__device__ int   g_csr[EE];
__device__ float g_sums[HDIM];
__device__ float g_sumsq[HDIM];

__device__ __forceinline__ float eluf(float x) { return x > 0.f ? x : (__expf(x) - 1.f); }
__device__ __forceinline__ float lrelu(float x) { return x > 0.f ? x : 0.2f * x; }

// ---------------- CSR build ------------------------------------------------
__global__ void k_zero_deg(int* deg) {
    int i = blockIdx.x * blockDim.x + threadIdx.x;
    if (i < NN) deg[i] = 0;
}

__global__ void k_hist(const int* __restrict__ dst, int* deg) {
    int i = blockIdx.x * blockDim.x + threadIdx.x;
    if (i < EE) atomicAdd(&deg[dst[i]], 1);
}

__global__ void k_scan(const int* __restrict__ deg, int* __restrict__ rowptr) {
    __shared__ int warp_sums[32];
    __shared__ int carry;
    int t = threadIdx.x, lane = t & 31, w = t >> 5;
    if (t == 0) { carry = 0; rowptr[0] = 0; }
    __syncthreads();
    for (int base = 0; base < NN; base += 1024) {
        int idx = base + t;
        int v = (idx < NN) ? deg[idx] : 0;
#pragma unroll
        for (int o = 1; o < 32; o <<= 1) {
            int u = __shfl_up_sync(0xffffffffu, v, o);
            if (lane >= o) v += u;
        }
        if (lane == 31) warp_sums[w] = v;
        __syncthreads();
        if (w == 0) {
            int s = warp_sums[lane];
#pragma unroll
            for (int o = 1; o < 32; o <<= 1) {
                int u = __shfl_up_sync(0xffffffffu, s, o);
                if (lane >= o) s += u;
            }
            warp_sums[lane] = s;
        }
        __syncthreads();
        int off = (w > 0) ? warp_sums[w - 1] : 0;
        int incl = v + off + carry;
        if (idx < NN) rowptr[idx + 1] = incl;
        __syncthreads();
        if (t == 0) carry += warp_sums[31];
        __syncthreads();
    }
}

__global__ void k_copy_cursor(const int* __restrict__ rowptr, int* cursor) {
    int i = blockIdx.x * blockDim.x + threadIdx.x;
    if (i < NN) cursor[i] = rowptr[i];
}

__global__ void k_fill(const int* __restrict__ src, const int* __restrict__ dst,
                       int* cursor, int* __restrict__ csr) {
    int i = blockIdx.x * blockDim.x + threadIdx.x;
    if (i < EE) {
        int d = dst[i];
        int pos = atomicAdd(&cursor[d], 1);
        csr[pos] = src[i];
    }
}

// ---------------- embedding gather -----------------------------------------
__global__ void k_embed(const int* __restrict__ x, const float* __restrict__ embed,
                        float* __restrict__ h) {
    int i = blockIdx.x * blockDim.x + threadIdx.x;
    if (i < NN * HDIM) {
        int n = i >> 7;
        h[i] = embed[x[n] * HDIM + (i & 127)];
    }
}

// ---------------- GEMM [N,128] @ [128,128] ---------------------------------
__global__ void k_gemm128(const float* __restrict__ A, const float* __restrict__ W,
                          float* __restrict__ C, int nrows) {
    __shared__ float Ws[32][128];
    __shared__ float As[64][33];
    int tid = threadIdx.x;
    int tx = tid & 31, ty = tid >> 5;
    int row0 = blockIdx.x * 64;
    float acc[8][4];
#pragma unroll
    for (int r = 0; r < 8; r++)
#pragma unroll
        for (int c = 0; c < 4; c++) acc[r][c] = 0.f;

    for (int kb = 0; kb < 4; kb++) {
        for (int i = tid; i < 4096; i += 256) {
            int kk = i >> 7, j = i & 127;
            Ws[kk][j] = W[(kb * 32 + kk) * 128 + j];
        }
        for (int i = tid; i < 2048; i += 256) {
            int r = i >> 5, kk = i & 31;
            int gr = row0 + r;
            As[r][kk] = (gr < nrows) ? A[gr * 128 + kb * 32 + kk] : 0.f;
        }
        __syncthreads();
#pragma unroll
        for (int kk = 0; kk < 32; kk++) {
            float b0 = Ws[kk][tx], b1 = Ws[kk][tx + 32];
            float b2 = Ws[kk][tx + 64], b3 = Ws[kk][tx + 96];
#pragma unroll
            for (int r = 0; r < 8; r++) {
                float a = As[ty + 8 * r][kk];
                acc[r][0] += a * b0;
                acc[r][1] += a * b1;
                acc[r][2] += a * b2;
                acc[r][3] += a * b3;
            }
        }
        __syncthreads();
    }
#pragma unroll
    for (int r = 0; r < 8; r++) {
        int gr = row0 + ty + 8 * r;
        if (gr < nrows) {
            C[gr * 128 + tx] = acc[r][0];
            C[gr * 128 + tx + 32] = acc[r][1];
            C[gr * 128 + tx + 64] = acc[r][2];
            C[gr * 128 + tx + 96] = acc[r][3];
        }
    }
}

// ---------------- el / er attention projections ----------------------------
__global__ void k_eler(const float* __restrict__ feat, const float* __restrict__ al,
                       const float* __restrict__ ar, float* __restrict__ el,
                       float* __restrict__ er) {
    int n = blockIdx.x * 2 + (threadIdx.x >> 7);
    int t = threadIdx.x & 127;
    int w = t >> 5;
    int lane = threadIdx.x & 31;
    float f = feat[n * HDIM + t];
    float pl = f * al[t];
    float pr = f * ar[t];
#pragma unroll
    for (int o = 16; o > 0; o >>= 1) {
        pl += __shfl_xor_sync(0xffffffffu, pl, o);
        pr += __shfl_xor_sync(0xffffffffu, pr, o);
    }
    if (lane == 0) {
        el[n * 4 + w] = pl;
        er[n * 4 + w] = pr;
    }
}

// ---------------- fused per-dst softmax + aggregation ----------------------
template <bool RES, bool ACT>
__global__ void k_agg(const float4* __restrict__ feat4, const float4* __restrict__ hin4,
                      const float4* __restrict__ el4, const float4* __restrict__ er4,
                      const float* __restrict__ snorm, const int* __restrict__ rowptr,
                      const int* __restrict__ csr, float4* __restrict__ out4) {
    int warp = (blockIdx.x * blockDim.x + threadIdx.x) >> 5;
    if (warp >= NN) return;
    int lane = threadIdx.x & 31;
    int start = rowptr[warp], end = rowptr[warp + 1];
    float4 er = er4[warp];

    float mx0 = -3e38f, mx1 = -3e38f, mx2 = -3e38f, mx3 = -3e38f;
    for (int k = start + lane; k < end; k += 32) {
        int s = csr[k];
        float4 e = el4[s];
        float v0 = lrelu(e.x + er.x), v1 = lrelu(e.y + er.y);
        float v2 = lrelu(e.z + er.z), v3 = lrelu(e.w + er.w);
        mx0 = fmaxf(mx0, v0); mx1 = fmaxf(mx1, v1);
        mx2 = fmaxf(mx2, v2); mx3 = fmaxf(mx3, v3);
    }
#pragma unroll
    for (int o = 16; o > 0; o >>= 1) {
        mx0 = fmaxf(mx0, __shfl_xor_sync(0xffffffffu, mx0, o));
        mx1 = fmaxf(mx1, __shfl_xor_sync(0xffffffffu, mx1, o));
        mx2 = fmaxf(mx2, __shfl_xor_sync(0xffffffffu, mx2, o));
        mx3 = fmaxf(mx3, __shfl_xor_sync(0xffffffffu, mx3, o));
    }
    float s0 = 0.f, s1 = 0.f, s2 = 0.f, s3 = 0.f;
    for (int k = start + lane; k < end; k += 32) {
        int s = csr[k];
        float4 e = el4[s];
        s0 += __expf(lrelu(e.x + er.x) - mx0);
        s1 += __expf(lrelu(e.y + er.y) - mx1);
        s2 += __expf(lrelu(e.z + er.z) - mx2);
        s3 += __expf(lrelu(e.w + er.w) - mx3);
    }
#pragma unroll
    for (int o = 16; o > 0; o >>= 1) {
        s0 += __shfl_xor_sync(0xffffffffu, s0, o);
        s1 += __shfl_xor_sync(0xffffffffu, s1, o);
        s2 += __shfl_xor_sync(0xffffffffu, s2, o);
        s3 += __shfl_xor_sync(0xffffffffu, s3, o);
    }
    float inv0 = 1.f / s0, inv1 = 1.f / s1, inv2 = 1.f / s2, inv3 = 1.f / s3;

    int hl = lane >> 3;  // head of this lane's float4 slot
    float mxh = hl == 0 ? mx0 : hl == 1 ? mx1 : hl == 2 ? mx2 : mx3;
    float invh = hl == 0 ? inv0 : hl == 1 ? inv1 : hl == 2 ? inv2 : inv3;
    float erh = hl == 0 ? er.x : hl == 1 ? er.y : hl == 2 ? er.z : er.w;

    float4 acc;
    if (RES) acc = hin4[warp * 32 + lane];
    else acc = make_float4(0.f, 0.f, 0.f, 0.f);

    for (int k = start; k < end; k++) {
        int s = csr[k];
        float4 e = el4[s];
        float ev = hl == 0 ? e.x : hl == 1 ? e.y : hl == 2 ? e.z : e.w;
        float a = __expf(lrelu(ev + erh) - mxh) * invh;
        float4 f = feat4[s * 32 + lane];
        acc.x += f.x * a; acc.y += f.y * a; acc.z += f.z * a; acc.w += f.w * a;
    }
    if (ACT) {
        acc.x = eluf(acc.x); acc.y = eluf(acc.y);
        acc.z = eluf(acc.z); acc.w = eluf(acc.w);
    }
    float sn = snorm[warp];
    acc.x *= sn; acc.y *= sn; acc.z *= sn; acc.w *= sn;
    out4[warp * 32 + lane] = acc;
}

// ---------------- BatchNorm ------------------------------------------------
__global__ void k_zero_stats(float* sums, float* sumsq) {
    int i = threadIdx.x;
    if (i < HDIM) { sums[i] = 0.f; sumsq[i] = 0.f; }
}

__global__ void k_bnstats(const float* __restrict__ h, float* sums, float* sumsq) {
    int ch = threadIdx.x;
    int r0 = blockIdx.x * 250;
    float s = 0.f, q = 0.f;
    for (int r = 0; r < 250; r++) {
        float v = h[(r0 + r) * HDIM + ch];
        s += v;
        q += v * v;
    }
    atomicAdd(&sums[ch], s);
    atomicAdd(&sumsq[ch], q);
}

__global__ void k_bnapply(float* __restrict__ h, const float* __restrict__ gamma,
                          const float* __restrict__ beta, const float* __restrict__ sums,
                          const float* __restrict__ sumsq) {
    int i = blockIdx.x * blockDim.x + threadIdx.x;
    if (i < NN * HDIM) {
        int ch = i & 127;
        float mu = sums[ch] * (1.f / NN);
        float var = sumsq[ch] * (1.f / NN) - mu * mu;
        float v = (h[i] - mu) * rsqrtf(var + 1e-5f) * gamma[ch] + beta[ch];
        h[i] = eluf(v);
    }
}

// ---------------- fused 2-layer classifier ---------------------------------
__global__ void k_cls(const float* __restrict__ H, const float* __restrict__ w1,
                      const float* __restrict__ b1, const float* __restrict__ w2,
                      const float* __restrict__ b2, float* __restrict__ out, int nrows) {
    __shared__ float Ws[32][64];
    __shared__ float As[64][33];
    __shared__ float Ts[64][65];
    int tid = threadIdx.x, tx = tid & 31, ty = tid >> 5;
    int row0 = blockIdx.x * 64;
    float acc[8][2];
#pragma unroll
    for (int r = 0; r < 8; r++) { acc[r][0] = 0.f; acc[r][1] = 0.f; }

    for (int kb = 0; kb < 4; kb++) {
        for (int i = tid; i < 2048; i += 256) {
            int kk = i >> 6, j = i & 63;
            Ws[kk][j] = w1[(kb * 32 + kk) * 64 + j];
        }
        for (int i = tid; i < 2048; i += 256) {
            int r = i >> 5, kk = i & 31;
            int gr = row0 + r;
            As[r][kk] = (gr < nrows) ? H[gr * 128 + kb * 32 + kk] : 0.f;
        }
        __syncthreads();
#pragma unroll
        for (int kk = 0; kk < 32; kk++) {
            float b0 = Ws[kk][tx], b1v = Ws[kk][tx + 32];
#pragma unroll
            for (int r = 0; r < 8; r++) {
                float a = As[ty + 8 * r][kk];
                acc[r][0] += a * b0;
                acc[r][1] += a * b1v;
            }
        }
        __syncthreads();
    }
    float bb0 = b1[tx], bb1 = b1[tx + 32];
#pragma unroll
    for (int r = 0; r < 8; r++) {
        float t0 = acc[r][0] + bb0;
        float t1 = acc[r][1] + bb1;
        Ts[ty + 8 * r][tx] = t0 > 0.f ? t0 : 0.f;
        Ts[ty + 8 * r][tx + 32] = t1 > 0.f ? t1 : 0.f;
    }
    __syncthreads();
    if (tid < 128) {
        int row = tid >> 1, o = tid & 1;
        float s = b2[o];
        for (int k = 0; k < 64; k++) s += Ts[row][k] * w2[k * 2 + o];
        int gr = row0 + row;
        if (gr < nrows) out[gr * 2 + o] = s;
    }
}

// ---------------- host orchestration ---------------------------------------
extern "C" void kernel_launch(void* const* d_in, const int* in_sizes, int n_in,
                              void* d_out, int out_size) {
    const int* x = (const int*)d_in[0];
    const int* src = (const int*)d_in[1];
    const int* dst = (const int*)d_in[2];
    const float* snorm_n = (const float*)d_in[3];
    // d_in[4] snorm_e: unused by the reference
    const float* embed = (const float*)d_in[5];
    const float* W[3] = {(const float*)d_in[6], (const float*)d_in[11], (const float*)d_in[16]};
    const float* al[3] = {(const float*)d_in[7], (const float*)d_in[12], (const float*)d_in[17]};
    const float* ar[3] = {(const float*)d_in[8], (const float*)d_in[13], (const float*)d_in[18]};
    const float* gamma[3] = {(const float*)d_in[9], (const float*)d_in[14], (const float*)d_in[19]};
    const float* beta[3] = {(const float*)d_in[10], (const float*)d_in[15], (const float*)d_in[20]};
    const float* cls1_w = (const float*)d_in[21];
    const float* cls1_b = (const float*)d_in[22];
    const float* cls2_w = (const float*)d_in[23];
    const float* cls2_b = (const float*)d_in[24];
    float* out = (float*)d_out;

    float *h0, *h1, *feat, *el, *er, *sums, *sumsq;
    int *deg, *rowptr, *cursor, *csr;
    cudaGetSymbolAddress((void**)&h0, g_h0);
    cudaGetSymbolAddress((void**)&h1, g_h1);
    cudaGetSymbolAddress((void**)&feat, g_feat);
    cudaGetSymbolAddress((void**)&el, g_el);
    cudaGetSymbolAddress((void**)&er, g_er);
    cudaGetSymbolAddress((void**)&deg, g_deg);
    cudaGetSymbolAddress((void**)&rowptr, g_rowptr);
    cudaGetSymbolAddress((void**)&cursor, g_cursor);
    cudaGetSymbolAddress((void**)&csr, g_csr);
    cudaGetSymbolAddress((void**)&sums, g_sums);
    cudaGetSymbolAddress((void**)&sumsq, g_sumsq);

    // CSR build (per replay; deterministic up to fp tolerance)
    k_zero_deg<<<(NN + 255) / 256, 256>>>(deg);
    k_hist<<<(EE + 255) / 256, 256>>>(dst, deg);
    k_scan<<<1, 1024>>>(deg, rowptr);
    k_copy_cursor<<<(NN + 255) / 256, 256>>>(rowptr, cursor);
    k_fill<<<(EE + 255) / 256, 256>>>(src, dst, cursor, csr);

    k_embed<<<(NN * HDIM + 255) / 256, 256>>>(x, embed, h0);

    float* hin = h0;
    float* hout = h1;
    for (int l = 0; l < 3; l++) {
        k_gemm128<<<(NN + 63) / 64, 256>>>(hin, W[l], feat, NN);
        k_eler<<<NN / 2, 256>>>(feat, al[l], ar[l], el, er);
        if (l == 0) {
            k_agg<false, false><<<(NN + 7) / 8, 256>>>(
                (const float4*)feat, (const float4*)hin, (const float4*)el,
                (const float4*)er, snorm_n, rowptr, csr, (float4*)hout);
        } else {
            k_agg<true, true><<<(NN + 7) / 8, 256>>>(
                (const float4*)feat, (const float4*)hin, (const float4*)el,
                (const float4*)er, snorm_n, rowptr, csr, (float4*)hout);
        }
        k_zero_stats<<<1, 128>>>(sums, sumsq);
        k_bnstats<<<200, 128>>>(hout, sums, sumsq);
        k_bnapply<<<(NN * HDIM + 255) / 256, 256>>>(hout, gamma[l], beta[l], sums, sumsq);
        float* tmp = hin; hin = hout; hout = tmp;
    }
    k_cls<<<(NN + 63) / 64, 256>>>(hin, cls1_w, cls1_b, cls2_w, cls2_b, out, NN);
}